// round 11
// baseline (speedup 1.0000x reference)
#include <cuda_runtime.h>
#include <math.h>

// ---------------------------------------------------------------------------
// ToRGB: out = tanh( (x * s[b]) @ k2d + bias ),  s = (w@affine_w + affine_b)/sqrt(512)
// Fold: keff[b,c,o] = s[b,c] * k2d[c,o]
// Main: R10 f32x2 2-px body at 5 CTAs/SM (40 warps) — testing whether
// memory-controller stream concurrency lifts the 77% DRAM plateau.
// ---------------------------------------------------------------------------

#define B_    8
#define CIN   512
#define WDIM  128
#define COUT  4
#define PIX   (128*128)
#define INV_SQRT_CIN 0.04419417382415922f

#define GRID_X          92               // 92*8 = 736 ~= 148 SMs * 5 CTAs
#define UNIT_PX         16               // 8 warps * 2 px
#define UNITS_PER_BATCH (PIX / UNIT_PX)  // 1024

typedef unsigned long long u64;

// folded per-batch kernel, PERMUTED (R6 scheme):
// c = lane*4 + j + i*128  ->  idx = (i*4 + j)*32 + lane
__device__ float4 g_keff[B_ * CIN];

// ---------------------------------------------------------------------------
// Prologue: grid=(8,8), block=(64,8). 64-channel chunks, 8 j-slices of 16.
// ---------------------------------------------------------------------------
__global__ void build_keff_kernel(const float* __restrict__ w,
                                  const float* __restrict__ affine_w,
                                  const float* __restrict__ affine_b,
                                  const float* __restrict__ k2d)
{
    const int b  = blockIdx.x;
    const int c  = blockIdx.y * 64 + threadIdx.x;
    const int js = threadIdx.y;                    // 0..7

    __shared__ float ws[WDIM];
    __shared__ float part[7][64];

    const int tid = threadIdx.y * 64 + threadIdx.x;
    if (tid < WDIM) ws[tid] = w[b * WDIM + tid];
    __syncthreads();

    float s = 0.f;
    const int j0 = js * 16;
    #pragma unroll
    for (int j = j0; j < j0 + 16; j++)
        s = fmaf(ws[j], affine_w[j * CIN + c], s);

    if (js > 0) part[js - 1][threadIdx.x] = s;
    __syncthreads();

    if (js == 0) {
        #pragma unroll
        for (int q = 0; q < 7; q++) s += part[q][threadIdx.x];
        s = (s + affine_b[c]) * INV_SQRT_CIN;
        float4 kk = *reinterpret_cast<const float4*>(k2d + c * COUT);
        float4 o;
        o.x = s * kk.x; o.y = s * kk.y; o.z = s * kk.z; o.w = s * kk.w;
        const int i = c >> 7, r = c & 127, lane = r >> 2, jj = r & 3;
        g_keff[b * CIN + (i * 4 + jj) * 32 + lane] = o;
    }
}

// ---------------------------------------------------------------------------
// f32x2 packed math helpers (sm_103a)
// ---------------------------------------------------------------------------
__device__ __forceinline__ u64 pack_f32x2(float lo, float hi) {
    u64 r;
    asm("mov.b64 %0, {%1, %2};" : "=l"(r) : "f"(lo), "f"(hi));
    return r;
}
__device__ __forceinline__ void unpack_f32x2(float& lo, float& hi, u64 v) {
    asm("mov.b64 {%0, %1}, %2;" : "=f"(lo), "=f"(hi) : "l"(v));
}
__device__ __forceinline__ u64 fma_f32x2(u64 a, u64 b, u64 c) {
    u64 d;
    asm("fma.rn.f32x2 %0, %1, %2, %3;" : "=l"(d) : "l"(a), "l"(b), "l"(c));
    return d;
}
__device__ __forceinline__ float tanh_fast(float x) {
    float r;
    asm("tanh.approx.f32 %0, %1;" : "=f"(r) : "f"(x));
    return r;
}

// packed pair reduction: two independent sums, one shuffle
__device__ __forceinline__ float pairstep(float a, float b, bool lo, int off)
{
    float send = lo ? b : a;
    float recv = __shfl_xor_sync(0xffffffffu, send, off);
    return (lo ? a : b) + recv;
}

// ---------------------------------------------------------------------------
// Main: grid=(92, 8), block=256 (8 warps), 5 CTAs/SM — one wave, 40 warps/SM.
// ---------------------------------------------------------------------------
__global__ void __launch_bounds__(256, 5)
torgb_main_kernel(const float* __restrict__ x,
                  const float* __restrict__ bias,
                  float* __restrict__ out)
{
    const int b    = blockIdx.y;
    const int warp = threadIdx.x >> 5;
    const int lane = threadIdx.x & 31;

    __shared__ __align__(16) float4 kws[CIN];   // 8 KB

    {
        const float4* gk = g_keff + b * CIN;
        kws[threadIdx.x]       = gk[threadIdx.x];
        kws[threadIdx.x + 256] = gk[threadIdx.x + 256];
    }
    __syncthreads();

    // keff as packed pairs: kwl2[idx].x = (k.x,k.y), .y = (k.z,k.w)
    const ulonglong2* kwl2 = reinterpret_cast<const ulonglong2*>(kws) + lane;

    // final packed-reduce slots (R2/R6-verified):
    // lanes with (lane&3)==0 store pixel p_off=bit4, output o_idx.
    const int   p_off  = (lane >> 4) & 1;
    const int   o_idx  = (((lane >> 2) & 1) << 1) | ((lane >> 3) & 1);
    const bool  storer = (lane & 3) == 0;
    const float mybias = bias[o_idx];
    const bool  lo16 = lane < 16;
    const bool  lo8  = (lane & 8) == 0;
    const bool  lo4  = (lane & 4) == 0;

    const long long px0 = (long long)b * PIX + (long long)blockIdx.x * UNIT_PX + warp * 2;
    const float4* xp = reinterpret_cast<const float4*>(x + px0 * CIN) + lane;
    float*        op = out + px0 * COUT + p_off * COUT + o_idx;

    const long long xstep = (long long)GRID_X * UNIT_PX * (CIN / 4);
    const long long ostep = (long long)GRID_X * UNIT_PX * COUT;

    #pragma unroll 1
    for (int u = blockIdx.x; u < UNITS_PER_BATCH; u += GRID_X) {
        // ---- 2 pixels: 8 LDG.128 (ptxas may split into 2 groups at 51 regs) ----
        float4 a[4], c4[4];
        #pragma unroll
        for (int i = 0; i < 4; i++) a[i]  = __ldcs(xp + i * 32);
        #pragma unroll
        for (int i = 0; i < 4; i++) c4[i] = __ldcs(xp + 128 + i * 32);

        // packed accumulators: p0a=(v0,v1) p0b=(v2,v3) p1a=(v4,v5) p1b=(v6,v7)
        u64 p0a = 0ull, p0b = 0ull, p1a = 0ull, p1b = 0ull;

        #pragma unroll
        for (int i = 0; i < 4; i++) {
            const float av[4] = {a[i].x,  a[i].y,  a[i].z,  a[i].w};
            const float cv[4] = {c4[i].x, c4[i].y, c4[i].z, c4[i].w};
            u64 ap[4], cp[4];
            #pragma unroll
            for (int j = 0; j < 4; j++) {
                ap[j] = pack_f32x2(av[j], av[j]);
                cp[j] = pack_f32x2(cv[j], cv[j]);
            }
            #pragma unroll
            for (int j = 0; j < 4; j++) {
                const ulonglong2 kk = kwl2[(i * 4 + j) * 32];   // LDS.128
                p0a = fma_f32x2(ap[j], kk.x, p0a);
                p0b = fma_f32x2(ap[j], kk.y, p0b);
                p1a = fma_f32x2(cp[j], kk.x, p1a);
                p1b = fma_f32x2(cp[j], kk.y, p1b);
            }
        }

        float v0, v1, v2, v3, v4, v5, v6, v7;
        unpack_f32x2(v0, v1, p0a);
        unpack_f32x2(v2, v3, p0b);
        unpack_f32x2(v4, v5, p1a);
        unpack_f32x2(v6, v7, p1b);

        // ---- packed butterfly: 8 sums in 9 shuffles (R6-verified) ----
        float r0 = pairstep(v0, v4, lo16, 16);
        float r1 = pairstep(v1, v5, lo16, 16);
        float r2 = pairstep(v2, v6, lo16, 16);
        float r3 = pairstep(v3, v7, lo16, 16);

        float s0 = pairstep(r0, r1, lo8, 8);
        float s1 = pairstep(r2, r3, lo8, 8);

        float t  = pairstep(s0, s1, lo4, 4);
        t += __shfl_xor_sync(0xffffffffu, t, 2);
        t += __shfl_xor_sync(0xffffffffu, t, 1);

        if (storer)
            *op = tanh_fast(t + mybias);

        xp += xstep;
        op += ostep;
    }
}

// ---------------------------------------------------------------------------
// inputs: x[8,128,128,512], w[8,128], affine_w[128,512], affine_b[512],
//         kernel[1,1,512,4], bias[4]  -> out[8,128,128,4] f32
// ---------------------------------------------------------------------------
extern "C" void kernel_launch(void* const* d_in, const int* in_sizes, int n_in,
                              void* d_out, int out_size)
{
    const float* x        = (const float*)d_in[0];
    const float* w        = (const float*)d_in[1];
    const float* affine_w = (const float*)d_in[2];
    const float* affine_b = (const float*)d_in[3];
    const float* k2d      = (const float*)d_in[4];
    const float* bias     = (const float*)d_in[5];
    float*       out      = (float*)d_out;

    dim3 pgrid(B_, 8), pblock(64, 8);
    build_keff_kernel<<<pgrid, pblock>>>(w, affine_w, affine_b, k2d);

    dim3 grid(GRID_X, B_);
    torgb_main_kernel<<<grid, 256>>>(x, bias, out);
}